// round 2
// baseline (speedup 1.0000x reference)
#include <cuda_runtime.h>

// ---------------- problem-size constants (fixed by the dataset) -------------
#define NMAX 100000
#define EMAX 3200000
#define PAD  128          // max in-degree slot per node (deg ~ Poisson(32); P(>128) ~ 0)

// ---------------- device scratch (no allocations allowed) -------------------
__device__ int    g_cursor[NMAX];        // per-node CSR write cursor (ends at segment end)
__device__ int    g_csr[NMAX * PAD];     // padded CSR: source ids of in-edges of node v at [v*PAD, cursor[v])
__device__ float  g_dinv[NMAX];          // rsqrt(deg+1)
__device__ float4 g_s1[NMAX * 4];        // s1[v] = (x[v]@W1) * dinv[v]   (16 floats as 4x float4)
__device__ float2 g_s2[NMAX];            // s2[v] = (h[v]@W2) * dinv[v]
__device__ float4 g_pA[NMAX];            // pA[v] = h[v] @ We[0:16]
__device__ float4 g_pB[NMAX];            // pB[v] = h[v] @ We[17:33]
__device__ int    g_idx64;               // 1 if edge_index is int64, 0 if int32

// ---------------- index-width detection -------------------------------------
__global__ void k_detect(const int* __restrict__ p) {
    if (blockIdx.x == 0 && threadIdx.x == 0) {
        int f = 1;
        #pragma unroll 1
        for (int i = 0; i < 64; i++) {
            if (p[2 * i + 1] != 0) { f = 0; break; }  // int64 hi-words are 0 (ids < 2^31)
        }
        g_idx64 = f;
    }
}

__device__ __forceinline__ int load_idx(const void* base, long long i, int is64) {
    if (is64) return (int)__ldg(((const long long*)base) + i);
    return __ldg(((const int*)base) + i);
}

// ---------------- K0: init cursors ------------------------------------------
__global__ void k_init(int n) {
    int v = blockIdx.x * blockDim.x + threadIdx.x;
    if (v < n) g_cursor[v] = v * PAD;
}

// ---------------- K1: build padded CSR (1 int atomic per edge) ---------------
__global__ void k_build(const void* __restrict__ ei, int E) {
    int e = blockIdx.x * blockDim.x + threadIdx.x;
    if (e >= E) return;
    int is64 = g_idx64;
    int r = load_idx(ei, e, is64);
    int c = load_idx(ei, (long long)E + e, is64);
    int p = atomicAdd(&g_cursor[c], 1);
    if (p < c * PAD + PAD) g_csr[p] = r;
}

// ---------------- K2: per-node dinv + s1 -------------------------------------
__global__ void k_node1(const float* __restrict__ x, const float* __restrict__ W1, int n) {
    int v = blockIdx.x * blockDim.x + threadIdx.x;
    if (v >= n) return;
    int deg = g_cursor[v] - v * PAD;             // in-degree (self loop handled by +1)
    float dinv = rsqrtf((float)(deg + 1));
    g_dinv[v] = dinv;
    float x0 = __ldg(&x[2 * v]), x1 = __ldg(&x[2 * v + 1]);
    #pragma unroll
    for (int q = 0; q < 4; q++) {
        float4 s;
        s.x = (x0 * __ldg(&W1[q * 4 + 0]) + x1 * __ldg(&W1[16 + q * 4 + 0])) * dinv;
        s.y = (x0 * __ldg(&W1[q * 4 + 1]) + x1 * __ldg(&W1[16 + q * 4 + 1])) * dinv;
        s.z = (x0 * __ldg(&W1[q * 4 + 2]) + x1 * __ldg(&W1[16 + q * 4 + 2])) * dinv;
        s.w = (x0 * __ldg(&W1[q * 4 + 3]) + x1 * __ldg(&W1[16 + q * 4 + 3])) * dinv;
        g_s1[v * 4 + q] = s;
    }
}

// ---------------- K3: layer-1 aggregate -> s2, pA, pB (h never stored) -------
// One warp per node. Lanes: group g = lane>>2 handles edge slots, quarter q = lane&3
// handles 4 features (one float4). Butterfly over groups, then per-quartet dot
// products against W2 / We halves.
__global__ void k_agg1(const float* __restrict__ We, const float* __restrict__ W2,
                       const float* __restrict__ b1, int n) {
    __shared__ float sWe[132], sW2[32], sB1[16];
    int t = threadIdx.x;
    if (t < 132) sWe[t] = We[t];
    if (t < 32)  sW2[t] = W2[t];
    if (t < 16)  sB1[t] = b1[t];
    __syncthreads();

    int v = (blockIdx.x * blockDim.x + t) >> 5;
    if (v >= n) return;
    int lane = t & 31, g = lane >> 2, q = lane & 3;
    int start = v * PAD, end = g_cursor[v];

    float4 acc = make_float4(0.f, 0.f, 0.f, 0.f);
    for (int p = start + g; p < end; p += 8) {
        int src = g_csr[p];                       // quartet-broadcast L1 hit
        float4 r = g_s1[src * 4 + q];             // 16B gather from L2-resident table
        acc.x += r.x; acc.y += r.y; acc.z += r.z; acc.w += r.w;
    }
    #pragma unroll
    for (int off = 4; off < 32; off <<= 1) {
        acc.x += __shfl_xor_sync(0xffffffffu, acc.x, off);
        acc.y += __shfl_xor_sync(0xffffffffu, acc.y, off);
        acc.z += __shfl_xor_sync(0xffffffffu, acc.z, off);
        acc.w += __shfl_xor_sync(0xffffffffu, acc.w, off);
    }
    float4 s1v = g_s1[v * 4 + q];
    float dv = g_dinv[v];
    float h[4];
    h[0] = dv * (acc.x + s1v.x) + sB1[q * 4 + 0];
    h[1] = dv * (acc.y + s1v.y) + sB1[q * 4 + 1];
    h[2] = dv * (acc.z + s1v.z) + sB1[q * 4 + 2];
    h[3] = dv * (acc.w + s1v.w) + sB1[q * 4 + 3];

    float d0 = 0.f, d1 = 0.f;
    float a0 = 0.f, a1 = 0.f, a2 = 0.f, a3 = 0.f;
    float p0 = 0.f, p1 = 0.f, p2 = 0.f, p3 = 0.f;
    #pragma unroll
    for (int i = 0; i < 4; i++) {
        int k = q * 4 + i;
        float hv = h[i];
        d0 += hv * sW2[k * 2 + 0];
        d1 += hv * sW2[k * 2 + 1];
        a0 += hv * sWe[k * 4 + 0];
        a1 += hv * sWe[k * 4 + 1];
        a2 += hv * sWe[k * 4 + 2];
        a3 += hv * sWe[k * 4 + 3];
        p0 += hv * sWe[(17 + k) * 4 + 0];
        p1 += hv * sWe[(17 + k) * 4 + 1];
        p2 += hv * sWe[(17 + k) * 4 + 2];
        p3 += hv * sWe[(17 + k) * 4 + 3];
    }
    #pragma unroll
    for (int off = 1; off < 4; off <<= 1) {
        d0 += __shfl_xor_sync(0xffffffffu, d0, off);
        d1 += __shfl_xor_sync(0xffffffffu, d1, off);
        a0 += __shfl_xor_sync(0xffffffffu, a0, off);
        a1 += __shfl_xor_sync(0xffffffffu, a1, off);
        a2 += __shfl_xor_sync(0xffffffffu, a2, off);
        a3 += __shfl_xor_sync(0xffffffffu, a3, off);
        p0 += __shfl_xor_sync(0xffffffffu, p0, off);
        p1 += __shfl_xor_sync(0xffffffffu, p1, off);
        p2 += __shfl_xor_sync(0xffffffffu, p2, off);
        p3 += __shfl_xor_sync(0xffffffffu, p3, off);
    }
    if (lane == 0) {
        g_s2[v] = make_float2(d0 * dv, d1 * dv);
        g_pA[v] = make_float4(a0, a1, a2, a3);
        g_pB[v] = make_float4(p0, p1, p2, p3);
    }
}

// ---------------- K4: layer-2 aggregate + node log_softmax -------------------
__global__ void k_agg2(const float* __restrict__ b2, float* __restrict__ out, int n) {
    int v = (blockIdx.x * blockDim.x + threadIdx.x) >> 5;
    if (v >= n) return;
    int lane = threadIdx.x & 31;
    int start = v * PAD, end = g_cursor[v];
    float a0 = 0.f, a1 = 0.f;
    for (int p = start + lane; p < end; p += 32) {
        int src = g_csr[p];
        float2 s = g_s2[src];
        a0 += s.x; a1 += s.y;
    }
    #pragma unroll
    for (int off = 16; off; off >>= 1) {
        a0 += __shfl_xor_sync(0xffffffffu, a0, off);
        a1 += __shfl_xor_sync(0xffffffffu, a1, off);
    }
    if (lane == 0) {
        float2 sv = g_s2[v];
        float dv = g_dinv[v];
        float o0 = dv * (a0 + sv.x) + __ldg(&b2[0]);
        float o1 = dv * (a1 + sv.y) + __ldg(&b2[1]);
        float m = fmaxf(o0, o1);
        float l = logf(expf(o0 - m) + expf(o1 - m));
        out[2 * v + 0] = o0 - m - l;
        out[2 * v + 1] = o1 - m - l;
    }
}

// ---------------- K5: edge MLP + log_softmax ---------------------------------
__global__ void k_edge(const void* __restrict__ ei, const float* __restrict__ ea,
                       const float* __restrict__ We, const float* __restrict__ be,
                       float* __restrict__ out, int E) {
    int e = blockIdx.x * blockDim.x + threadIdx.x;
    if (e >= E) return;
    int is64 = g_idx64;
    int r = load_idx(ei, e, is64);
    int c = load_idx(ei, (long long)E + e, is64);
    float a = __ldg(&ea[e]);
    float4 pa = g_pA[r];            // 16B gathers, hot 1.6MB tables in L2
    float4 pb = g_pB[c];
    float t0 = pa.x + pb.x + a * __ldg(&We[64 + 0]) + __ldg(&be[0]);
    float t1 = pa.y + pb.y + a * __ldg(&We[64 + 1]) + __ldg(&be[1]);
    float t2 = pa.z + pb.z + a * __ldg(&We[64 + 2]) + __ldg(&be[2]);
    float t3 = pa.w + pb.w + a * __ldg(&We[64 + 3]) + __ldg(&be[3]);
    t0 = fmaxf(t0, 0.f); t1 = fmaxf(t1, 0.f);
    t2 = fmaxf(t2, 0.f); t3 = fmaxf(t3, 0.f);
    float m = fmaxf(fmaxf(t0, t1), fmaxf(t2, t3));
    float s = expf(t0 - m) + expf(t1 - m) + expf(t2 - m) + expf(t3 - m);
    float l = m + logf(s);
    float4 o = make_float4(t0 - l, t1 - l, t2 - l, t3 - l);
    ((float4*)out)[e] = o;
}

// ---------------- launch ------------------------------------------------------
extern "C" void kernel_launch(void* const* d_in, const int* in_sizes, int n_in,
                              void* d_out, int out_size) {
    const float* x  = (const float*)d_in[0];
    const void*  ei = d_in[1];
    const float* ea = (const float*)d_in[2];
    const float* W1 = (const float*)d_in[3];
    const float* b1 = (const float*)d_in[4];
    const float* We = (const float*)d_in[5];
    const float* be = (const float*)d_in[6];
    const float* W2 = (const float*)d_in[7];
    const float* b2 = (const float*)d_in[8];

    int n = in_sizes[0] / 2;
    int E = in_sizes[1] / 2;
    float* outN = (float*)d_out;
    float* outE = outN + 2 * (size_t)n;

    const int TB = 256;
    k_detect<<<1, 32>>>((const int*)ei);
    k_init  <<<(n + TB - 1) / TB, TB>>>(n);
    k_build <<<(E + TB - 1) / TB, TB>>>(ei, E);
    k_node1 <<<(n + TB - 1) / TB, TB>>>(x, W1, n);
    int warpsPerBlk = TB / 32;
    k_agg1  <<<(n + warpsPerBlk - 1) / warpsPerBlk, TB>>>(We, W2, b1, n);
    k_agg2  <<<(n + warpsPerBlk - 1) / warpsPerBlk, TB>>>(b2, outN, n);
    k_edge  <<<(E + TB - 1) / TB, TB>>>(ei, ea, We, be, outE, E);
}

// round 3
// speedup vs baseline: 1.1032x; 1.1032x over previous
#include <cuda_runtime.h>

// ---------------- problem-size constants (fixed by the dataset) -------------
#define NMAX 100000
#define EMAX 3200000
#define PAD  128          // max in-degree slot per node (deg ~ Binomial, mean 32, std 5.7)

// ---------------- device scratch (no allocations allowed) -------------------
__device__ int    g_cursor[NMAX];        // per-node CSR write cursor
__device__ int    g_csr[NMAX * PAD];     // padded CSR: sources of in-edges of node v at [v*PAD, ...)
__device__ float  g_dinv[NMAX];          // rsqrt(deg+1)
__device__ float2 g_y[NMAX];             // y[v] = x[v] * dinv[v]   (2-dim pre-projection aggregate!)
__device__ float2 g_s2[NMAX];            // s2[v] = (h[v]@W2) * dinv[v]
__device__ float4 g_pA[NMAX];            // pA[v] = h[v] @ We[0:16]
__device__ float4 g_pB[NMAX];            // pB[v] = h[v] @ We[17:33]
__device__ int    g_idx64;               // 1 if edge_index is int64, 0 if int32

__device__ __forceinline__ int load_idx(const void* base, long long i, int is64) {
    if (is64) return (int)__ldg(((const long long*)base) + i);
    return __ldg(((const int*)base) + i);
}

// ---------------- K0: init cursors + index-width detection -------------------
__global__ void k_init(const int* __restrict__ p, int n) {
    int v = blockIdx.x * blockDim.x + threadIdx.x;
    if (v < n) g_cursor[v] = v * PAD;
    if (blockIdx.x == 0 && threadIdx.x == 0) {
        int f = 1;
        #pragma unroll 1
        for (int i = 0; i < 64; i++) {
            if (p[2 * i + 1] != 0) { f = 0; break; }  // int64 hi-words are 0 (ids < 2^31)
        }
        g_idx64 = f;
    }
}

// ---------------- K1: build padded CSR (1 int atomic per edge) ---------------
__global__ void k_build(const void* __restrict__ ei, int E) {
    int e = blockIdx.x * blockDim.x + threadIdx.x;
    if (e >= E) return;
    int is64 = g_idx64;
    int r = load_idx(ei, e, is64);
    int c = load_idx(ei, (long long)E + e, is64);
    int p = atomicAdd(&g_cursor[c], 1);
    if (p < c * PAD + PAD) g_csr[p] = r;
}

// ---------------- K2: per-node dinv + y = x*dinv -----------------------------
__global__ void k_node1(const float* __restrict__ x, int n) {
    int v = blockIdx.x * blockDim.x + threadIdx.x;
    if (v >= n) return;
    int deg = g_cursor[v] - v * PAD;
    float dinv = rsqrtf((float)(deg + 1));
    g_dinv[v] = dinv;
    float2 xv = ((const float2*)x)[v];
    g_y[v] = make_float2(xv.x * dinv, xv.y * dinv);
}

// ---------------- K3: aggregate y (2-dim), then project -> s2, pA, pB --------
// One warp per node. 32 lanes gather 8B each from the hot 800KB y-table,
// butterfly-reduce, then lanes 0..15 each own one of the 16 hidden features for
// the epilogue projections (W2, We halves), reduced over 16 lanes.
__global__ void k_agg1(const float* __restrict__ W1, const float* __restrict__ b1,
                       const float* __restrict__ We, const float* __restrict__ W2,
                       int n) {
    __shared__ float sW1[32], sB1[16], sWe[132], sW2[32];
    int t = threadIdx.x;
    if (t < 132) sWe[t] = We[t];
    if (t < 32)  { sW1[t] = W1[t]; sW2[t] = W2[t]; }
    if (t < 16)  sB1[t] = b1[t];
    __syncthreads();

    int v = (blockIdx.x * blockDim.x + t) >> 5;
    if (v >= n) return;
    int lane = t & 31;
    int start = v * PAD;
    int end = min(g_cursor[v], start + PAD);

    float ax = 0.f, ay = 0.f;
    for (int p = start + lane; p < end; p += 32) {
        float2 yu = g_y[g_csr[p]];       // 8B gather, table is L2-hot (800KB)
        ax += yu.x; ay += yu.y;
    }
    #pragma unroll
    for (int off = 16; off; off >>= 1) {
        ax += __shfl_xor_sync(0xffffffffu, ax, off);
        ay += __shfl_xor_sync(0xffffffffu, ay, off);
    }

    float dv = g_dinv[v];
    float2 yv = g_y[v];
    ax += yv.x; ay += yv.y;              // self-loop

    // lanes 0..15: feature q of h
    int q = lane & 15;
    float hq = dv * (ax * sW1[q] + ay * sW1[16 + q]) + sB1[q];

    float d0 = hq * sW2[q * 2 + 0];
    float d1 = hq * sW2[q * 2 + 1];
    float a0 = hq * sWe[q * 4 + 0];
    float a1 = hq * sWe[q * 4 + 1];
    float a2 = hq * sWe[q * 4 + 2];
    float a3 = hq * sWe[q * 4 + 3];
    float p0 = hq * sWe[(17 + q) * 4 + 0];
    float p1 = hq * sWe[(17 + q) * 4 + 1];
    float p2 = hq * sWe[(17 + q) * 4 + 2];
    float p3 = hq * sWe[(17 + q) * 4 + 3];
    #pragma unroll
    for (int off = 1; off < 16; off <<= 1) {   // xor offsets 1..8 keep lanes<16 closed
        d0 += __shfl_xor_sync(0xffffffffu, d0, off);
        d1 += __shfl_xor_sync(0xffffffffu, d1, off);
        a0 += __shfl_xor_sync(0xffffffffu, a0, off);
        a1 += __shfl_xor_sync(0xffffffffu, a1, off);
        a2 += __shfl_xor_sync(0xffffffffu, a2, off);
        a3 += __shfl_xor_sync(0xffffffffu, a3, off);
        p0 += __shfl_xor_sync(0xffffffffu, p0, off);
        p1 += __shfl_xor_sync(0xffffffffu, p1, off);
        p2 += __shfl_xor_sync(0xffffffffu, p2, off);
        p3 += __shfl_xor_sync(0xffffffffu, p3, off);
    }
    if (lane == 0) {
        g_s2[v] = make_float2(d0 * dv, d1 * dv);
        g_pA[v] = make_float4(a0, a1, a2, a3);
        g_pB[v] = make_float4(p0, p1, p2, p3);
    }
}

// ---------------- K4: layer-2 aggregate + node log_softmax -------------------
__global__ void k_agg2(const float* __restrict__ b2, float* __restrict__ out, int n) {
    int v = (blockIdx.x * blockDim.x + threadIdx.x) >> 5;
    if (v >= n) return;
    int lane = threadIdx.x & 31;
    int start = v * PAD;
    int end = min(g_cursor[v], start + PAD);
    float a0 = 0.f, a1 = 0.f;
    for (int p = start + lane; p < end; p += 32) {
        float2 s = g_s2[g_csr[p]];
        a0 += s.x; a1 += s.y;
    }
    #pragma unroll
    for (int off = 16; off; off >>= 1) {
        a0 += __shfl_xor_sync(0xffffffffu, a0, off);
        a1 += __shfl_xor_sync(0xffffffffu, a1, off);
    }
    if (lane == 0) {
        float2 sv = g_s2[v];
        float dv = g_dinv[v];
        float o0 = dv * (a0 + sv.x) + __ldg(&b2[0]);
        float o1 = dv * (a1 + sv.y) + __ldg(&b2[1]);
        float m = fmaxf(o0, o1);
        float l = logf(expf(o0 - m) + expf(o1 - m));
        ((float2*)out)[v] = make_float2(o0 - m - l, o1 - m - l);
    }
}

// ---------------- K5: edge MLP + log_softmax ---------------------------------
__global__ void k_edge(const void* __restrict__ ei, const float* __restrict__ ea,
                       const float* __restrict__ We, const float* __restrict__ be,
                       float* __restrict__ out, int E) {
    int e = blockIdx.x * blockDim.x + threadIdx.x;
    if (e >= E) return;
    int is64 = g_idx64;
    int r = load_idx(ei, e, is64);
    int c = load_idx(ei, (long long)E + e, is64);
    float a = __ldg(&ea[e]);
    float4 pa = g_pA[r];            // 16B gathers, 1.6MB hot tables in L2
    float4 pb = g_pB[c];
    float t0 = pa.x + pb.x + a * __ldg(&We[64 + 0]) + __ldg(&be[0]);
    float t1 = pa.y + pb.y + a * __ldg(&We[64 + 1]) + __ldg(&be[1]);
    float t2 = pa.z + pb.z + a * __ldg(&We[64 + 2]) + __ldg(&be[2]);
    float t3 = pa.w + pb.w + a * __ldg(&We[64 + 3]) + __ldg(&be[3]);
    t0 = fmaxf(t0, 0.f); t1 = fmaxf(t1, 0.f);
    t2 = fmaxf(t2, 0.f); t3 = fmaxf(t3, 0.f);
    float m = fmaxf(fmaxf(t0, t1), fmaxf(t2, t3));
    float s = expf(t0 - m) + expf(t1 - m) + expf(t2 - m) + expf(t3 - m);
    float l = m + logf(s);
    ((float4*)out)[e] = make_float4(t0 - l, t1 - l, t2 - l, t3 - l);
}

// ---------------- launch ------------------------------------------------------
extern "C" void kernel_launch(void* const* d_in, const int* in_sizes, int n_in,
                              void* d_out, int out_size) {
    const float* x  = (const float*)d_in[0];
    const void*  ei = d_in[1];
    const float* ea = (const float*)d_in[2];
    const float* W1 = (const float*)d_in[3];
    const float* b1 = (const float*)d_in[4];
    const float* We = (const float*)d_in[5];
    const float* be = (const float*)d_in[6];
    const float* W2 = (const float*)d_in[7];
    const float* b2 = (const float*)d_in[8];

    int n = in_sizes[0] / 2;
    int E = in_sizes[1] / 2;
    float* outN = (float*)d_out;
    float* outE = outN + 2 * (size_t)n;

    const int TB = 256;
    const int warpsPerBlk = TB / 32;
    k_init  <<<(n + TB - 1) / TB, TB>>>((const int*)ei, n);
    k_build <<<(E + TB - 1) / TB, TB>>>(ei, E);
    k_node1 <<<(n + TB - 1) / TB, TB>>>(x, n);
    k_agg1  <<<(n + warpsPerBlk - 1) / warpsPerBlk, TB>>>(W1, b1, We, W2, n);
    k_agg2  <<<(n + warpsPerBlk - 1) / warpsPerBlk, TB>>>(b2, outN, n);
    k_edge  <<<(E + TB - 1) / TB, TB>>>(ei, ea, We, be, outE, E);
}

// round 7
// speedup vs baseline: 1.1881x; 1.0769x over previous
#include <cuda_runtime.h>

// ---------------- problem-size constants (fixed by the dataset) -------------
#define NMAX 100000
#define EMAX 3200000
#define PAD  128          // max in-degree slot (deg ~ Binomial, mean 32, std 5.7)

// ---------------- device scratch (no allocations allowed) -------------------
__device__ int    g_cursor[NMAX];        // per-node CSR write cursor
__device__ int    g_csr[NMAX * PAD];     // padded CSR: sources of in-edges of node v
__device__ float  g_dinv[NMAX];          // rsqrt(deg+1)
__device__ float2 g_y[NMAX];             // y[v] = x[v] * dinv[v]
__device__ float2 g_s2[NMAX];            // s2[v] = (h[v]@W2) * dinv[v]
__device__ float4 g_pA[NMAX];            // pA[v] = h[v] @ We[0:16]
__device__ float4 g_pB[NMAX];            // pB[v] = h[v] @ We[17:33]
__device__ int    g_idx64;               // 1 if edge_index is int64

// composed linear coefficients (epilogue of layer 1 is linear in (ax,ay))
__device__ float  g_M2[4], g_c2[2];      // W1@W2 (2x2), b1@W2
__device__ float  g_MA[8], g_cA[4];      // W1@We[0:16] (2x4), b1@We[0:16]
__device__ float  g_MB[8], g_cB[4];      // W1@We[17:33] (2x4), b1@We[17:33]

__device__ __forceinline__ int load_idx(const void* base, long long i, int is64) {
    if (is64) return (int)__ldg(((const long long*)base) + i);
    return __ldg(((const int*)base) + i);
}

// ---------------- K-1: compose projection matrices (32 threads) --------------
__global__ void k_prep(const float* __restrict__ W1, const float* __restrict__ b1,
                       const float* __restrict__ We, const float* __restrict__ W2) {
    int t = threadIdx.x;
    if (t < 4) {                       // M2[i*2+j] = sum_q W1[i,q] W2[q,j]
        int i = t >> 1, j = t & 1;
        float s = 0.f;
        #pragma unroll
        for (int q = 0; q < 16; q++) s += W1[i * 16 + q] * W2[q * 2 + j];
        g_M2[t] = s;
    } else if (t < 6) {                // c2[j] = sum_q b1[q] W2[q,j]
        int j = t - 4;
        float s = 0.f;
        #pragma unroll
        for (int q = 0; q < 16; q++) s += b1[q] * W2[q * 2 + j];
        g_c2[j] = s;
    } else if (t < 14) {               // MA[i*4+j] = sum_q W1[i,q] We[q,j]
        int u = t - 6, i = u >> 2, j = u & 3;
        float s = 0.f;
        #pragma unroll
        for (int q = 0; q < 16; q++) s += W1[i * 16 + q] * We[q * 4 + j];
        g_MA[u] = s;
    } else if (t < 18) {               // cA[j] = sum_q b1[q] We[q,j]
        int j = t - 14;
        float s = 0.f;
        #pragma unroll
        for (int q = 0; q < 16; q++) s += b1[q] * We[q * 4 + j];
        g_cA[j] = s;
    } else if (t < 26) {               // MB[i*4+j] = sum_q W1[i,q] We[17+q,j]
        int u = t - 18, i = u >> 2, j = u & 3;
        float s = 0.f;
        #pragma unroll
        for (int q = 0; q < 16; q++) s += W1[i * 16 + q] * We[(17 + q) * 4 + j];
        g_MB[u] = s;
    } else if (t < 30) {               // cB[j] = sum_q b1[q] We[17+q,j]
        int j = t - 26;
        float s = 0.f;
        #pragma unroll
        for (int q = 0; q < 16; q++) s += b1[q] * We[(17 + q) * 4 + j];
        g_cB[j] = s;
    }
}

// ---------------- K0: init cursors + index-width detection -------------------
__global__ void k_init(const int* __restrict__ p, int n) {
    int v = blockIdx.x * blockDim.x + threadIdx.x;
    if (v < n) g_cursor[v] = v * PAD;
    if (blockIdx.x == 0 && threadIdx.x == 0) {
        int f = 1;
        #pragma unroll 1
        for (int i = 0; i < 64; i++) {
            if (p[2 * i + 1] != 0) { f = 0; break; }
        }
        g_idx64 = f;
    }
}

// ---------------- K1: build padded CSR (1 int atomic per edge) ---------------
__global__ void k_build(const void* __restrict__ ei, int E) {
    int e = blockIdx.x * blockDim.x + threadIdx.x;
    if (e >= E) return;
    int is64 = g_idx64;
    int r = load_idx(ei, e, is64);
    int c = load_idx(ei, (long long)E + e, is64);
    int p = atomicAdd(&g_cursor[c], 1);
    if (p < c * PAD + PAD) g_csr[p] = r;
}

// ---------------- K2: per-node dinv + y = x*dinv -----------------------------
__global__ void k_node1(const float* __restrict__ x, int n) {
    int v = blockIdx.x * blockDim.x + threadIdx.x;
    if (v >= n) return;
    int deg = g_cursor[v] - v * PAD;
    float dinv = rsqrtf((float)(deg + 1));
    g_dinv[v] = dinv;
    float2 xv = ((const float2*)x)[v];
    g_y[v] = make_float2(xv.x * dinv, xv.y * dinv);
}

// ---------------- K3: aggregate y (2-dim), composed epilogue -----------------
// One warp per node: 32 lanes gather 8B each from the L2-hot y-table, one
// 2-variable butterfly, then lane 0 computes s2/pA/pB with ~40 FMAs.
__global__ void k_agg1(int n) {
    int t = threadIdx.x;
    int v = (blockIdx.x * blockDim.x + t) >> 5;
    if (v >= n) return;
    int lane = t & 31;
    int start = v * PAD;
    int end = min(g_cursor[v], start + PAD);

    // prefetch self terms early (independent of gather loop)
    float dv = g_dinv[v];
    float2 yv = g_y[v];

    float ax = 0.f, ay = 0.f;
    for (int p = start + lane; p < end; p += 32) {
        float2 yu = g_y[g_csr[p]];
        ax += yu.x; ay += yu.y;
    }
    #pragma unroll
    for (int off = 16; off; off >>= 1) {
        ax += __shfl_xor_sync(0xffffffffu, ax, off);
        ay += __shfl_xor_sync(0xffffffffu, ay, off);
    }

    if (lane == 0) {
        ax += yv.x; ay += yv.y;          // self-loop
        float d2 = dv * dv;
        float2 s2;
        s2.x = d2 * (ax * g_M2[0] + ay * g_M2[2]) + dv * g_c2[0];
        s2.y = d2 * (ax * g_M2[1] + ay * g_M2[3]) + dv * g_c2[1];
        g_s2[v] = s2;
        float4 pa, pb;
        pa.x = dv * (ax * g_MA[0] + ay * g_MA[4]) + g_cA[0];
        pa.y = dv * (ax * g_MA[1] + ay * g_MA[5]) + g_cA[1];
        pa.z = dv * (ax * g_MA[2] + ay * g_MA[6]) + g_cA[2];
        pa.w = dv * (ax * g_MA[3] + ay * g_MA[7]) + g_cA[3];
        g_pA[v] = pa;
        pb.x = dv * (ax * g_MB[0] + ay * g_MB[4]) + g_cB[0];
        pb.y = dv * (ax * g_MB[1] + ay * g_MB[5]) + g_cB[1];
        pb.z = dv * (ax * g_MB[2] + ay * g_MB[6]) + g_cB[2];
        pb.w = dv * (ax * g_MB[3] + ay * g_MB[7]) + g_cB[3];
        g_pB[v] = pb;
    }
}

// ---------------- K4: layer-2 aggregate + node log_softmax -------------------
__global__ void k_agg2(const float* __restrict__ b2, float* __restrict__ out, int n) {
    int t = threadIdx.x;
    int v = (blockIdx.x * blockDim.x + t) >> 5;
    if (v >= n) return;
    int lane = t & 31;
    int start = v * PAD;
    int end = min(g_cursor[v], start + PAD);
    float dv = g_dinv[v];
    float2 sv = g_s2[v];
    float a0 = 0.f, a1 = 0.f;
    for (int p = start + lane; p < end; p += 32) {
        float2 s = g_s2[g_csr[p]];
        a0 += s.x; a1 += s.y;
    }
    #pragma unroll
    for (int off = 16; off; off >>= 1) {
        a0 += __shfl_xor_sync(0xffffffffu, a0, off);
        a1 += __shfl_xor_sync(0xffffffffu, a1, off);
    }
    if (lane == 0) {
        float o0 = dv * (a0 + sv.x) + __ldg(&b2[0]);
        float o1 = dv * (a1 + sv.y) + __ldg(&b2[1]);
        float m = fmaxf(o0, o1);
        float l = logf(expf(o0 - m) + expf(o1 - m));
        ((float2*)out)[v] = make_float2(o0 - m - l, o1 - m - l);
    }
}

// ---------------- K5: edge MLP + log_softmax ---------------------------------
__global__ void k_edge(const void* __restrict__ ei, const float* __restrict__ ea,
                       const float* __restrict__ We, const float* __restrict__ be,
                       float* __restrict__ out, int E) {
    int e = blockIdx.x * blockDim.x + threadIdx.x;
    if (e >= E) return;
    int is64 = g_idx64;
    int r = load_idx(ei, e, is64);
    int c = load_idx(ei, (long long)E + e, is64);
    float a = __ldg(&ea[e]);
    float4 pa = g_pA[r];
    float4 pb = g_pB[c];
    float t0 = pa.x + pb.x + a * __ldg(&We[64 + 0]) + __ldg(&be[0]);
    float t1 = pa.y + pb.y + a * __ldg(&We[64 + 1]) + __ldg(&be[1]);
    float t2 = pa.z + pb.z + a * __ldg(&We[64 + 2]) + __ldg(&be[2]);
    float t3 = pa.w + pb.w + a * __ldg(&We[64 + 3]) + __ldg(&be[3]);
    t0 = fmaxf(t0, 0.f); t1 = fmaxf(t1, 0.f);
    t2 = fmaxf(t2, 0.f); t3 = fmaxf(t3, 0.f);
    float m = fmaxf(fmaxf(t0, t1), fmaxf(t2, t3));
    float s = expf(t0 - m) + expf(t1 - m) + expf(t2 - m) + expf(t3 - m);
    float l = m + logf(s);
    ((float4*)out)[e] = make_float4(t0 - l, t1 - l, t2 - l, t3 - l);
}

// ---------------- launch ------------------------------------------------------
extern "C" void kernel_launch(void* const* d_in, const int* in_sizes, int n_in,
                              void* d_out, int out_size) {
    const float* x  = (const float*)d_in[0];
    const void*  ei = d_in[1];
    const float* ea = (const float*)d_in[2];
    const float* W1 = (const float*)d_in[3];
    const float* b1 = (const float*)d_in[4];
    const float* We = (const float*)d_in[5];
    const float* be = (const float*)d_in[6];
    const float* W2 = (const float*)d_in[7];
    const float* b2 = (const float*)d_in[8];

    int n = in_sizes[0] / 2;
    int E = in_sizes[1] / 2;
    float* outN = (float*)d_out;
    float* outE = outN + 2 * (size_t)n;

    const int TB = 256;
    const int warpsPerBlk = TB / 32;
    k_prep  <<<1, 32>>>(W1, b1, We, W2);
    k_init  <<<(n + TB - 1) / TB, TB>>>((const int*)ei, n);
    k_build <<<(E + TB - 1) / TB, TB>>>(ei, E);
    k_node1 <<<(n + TB - 1) / TB, TB>>>(x, n);
    k_agg1  <<<(n + warpsPerBlk - 1) / warpsPerBlk, TB>>>(n);
    k_agg2  <<<(n + warpsPerBlk - 1) / warpsPerBlk, TB>>>(b2, outN, n);
    k_edge  <<<(E + TB - 1) / TB, TB>>>(ei, ea, We, be, outE, E);
}